// round 2
// baseline (speedup 1.0000x reference)
#include <cuda_runtime.h>

#define N_NODES 32768
#define N_EDGES 160000
#define DIM     768
#define N_REL   3
#define H1      4
#define O1      192
#define H2      1
#define O2      768

// ---------------- scratch (device globals; no allocation allowed) ----------------
__device__ float g_xr[(size_t)N_REL * N_NODES * DIM];   // per-relation transformed feats
__device__ float g_h [(size_t)N_NODES * DIM];           // layer-1 output
__device__ float g_Q [N_REL * N_NODES * H1];
__device__ float g_K [N_REL * N_NODES * H1];
__device__ float g_alpha[N_EDGES * H1];
__device__ int   g_src[N_EDGES], g_dst[N_EDGES], g_et[N_EDGES];
__device__ int   g_deg[N_NODES];
__device__ int   g_off[N_NODES + 1];
__device__ int   g_pos[N_NODES];
__device__ int   g_eperm[N_EDGES];

// ---------------- f32x2 packed-FMA helpers (Blackwell dual-rate fp32) ----------------
__device__ __forceinline__ unsigned long long pk2(float x) {
    unsigned long long r;
    asm("mov.b64 %0, {%1, %1};" : "=l"(r) : "f"(x));
    return r;
}
__device__ __forceinline__ void fma2(unsigned long long& d, unsigned long long a,
                                     unsigned long long b) {
    asm("fma.rn.f32x2 %0, %1, %2, %0;" : "+l"(d) : "l"(a), "l"(b));
}

// ---------------- edge preprocessing ----------------
__global__ void k_zero_deg() {
    int i = blockIdx.x * blockDim.x + threadIdx.x;
    if (i < N_NODES) g_deg[i] = 0;
}

// edge_index / edge_type arrive as int32 (harness dtype universe is f32/i32/bf16)
__global__ void k_prep_edges(const int* __restrict__ ei,
                             const int* __restrict__ et) {
    int e = blockIdx.x * blockDim.x + threadIdx.x;
    if (e >= N_EDGES) return;
    int s = ei[e]          & (N_NODES - 1);   // mask-clamp: no-op for valid input
    int d = ei[N_EDGES + e] & (N_NODES - 1);
    int t = et[e];
    t = (t < 0) ? 0 : (t >= N_REL ? N_REL - 1 : t);
    g_src[e] = s;
    g_dst[e] = d;
    g_et[e]  = t;
    atomicAdd(&g_deg[d], 1);
}

// single-block exclusive scan of g_deg -> g_off, g_pos  (N_NODES = 1024*32)
__global__ void k_scan() {
    __shared__ int ps[1024];
    int tid = threadIdx.x;
    int base = tid * 32;
    int local[32];
    int s = 0;
#pragma unroll
    for (int j = 0; j < 32; j++) { local[j] = g_deg[base + j]; s += local[j]; }
    ps[tid] = s;
    __syncthreads();
    for (int st = 1; st < 1024; st <<= 1) {
        int v = (tid >= st) ? ps[tid - st] : 0;
        __syncthreads();
        ps[tid] += v;
        __syncthreads();
    }
    int run = ps[tid] - s;  // exclusive prefix
#pragma unroll
    for (int j = 0; j < 32; j++) {
        g_off[base + j] = run;
        g_pos[base + j] = run;
        run += local[j];
    }
    if (tid == 1023) g_off[N_NODES] = run;
}

__global__ void k_scatter() {
    int e = blockIdx.x * blockDim.x + threadIdx.x;
    if (e >= N_EDGES) return;
    int p = atomicAdd(&g_pos[g_dst[e]], 1);
    g_eperm[p] = e;
}

// ---------------- fp32 GEMM: g_xr[r] = A @ W[r]  (A: [32768,768], W[r]: [768,768]) ----------------
template <bool FROM_H>
__global__ __launch_bounds__(256, 2) void k_gemm(const float* __restrict__ Ain,
                                                 const float* __restrict__ Wall) {
    const float* A = FROM_H ? g_h : Ain;
    const float* B = Wall + (size_t)blockIdx.z * DIM * DIM;
    float* C = g_xr + (size_t)blockIdx.z * N_NODES * DIM;

    __shared__ float As[16][132];
    __shared__ float Bs[16][132];

    const int bm = blockIdx.y * 128, bn = blockIdx.x * 128;
    const int t  = threadIdx.x;
    const int tm = t >> 4, tn = t & 15;

    // loader coordinates
    const int ar0 = t >> 2,        ac0 = (t & 3) * 4;    // ar1 = ar0+64
    const int br0 = t >> 5,        bc0 = (t & 31) * 4;   // br1 = br0+8

    unsigned long long acc[8][4];
#pragma unroll
    for (int i = 0; i < 8; i++)
#pragma unroll
        for (int j = 0; j < 4; j++) acc[i][j] = 0ull;

    float4 aR0, aR1, bR0, bR1;

    auto load_g = [&](int k0) {
        aR0 = *(const float4*)(A + (size_t)(bm + ar0) * DIM + k0 + ac0);
        aR1 = *(const float4*)(A + (size_t)(bm + ar0 + 64) * DIM + k0 + ac0);
        bR0 = *(const float4*)(B + (size_t)(k0 + br0) * DIM + bn + bc0);
        bR1 = *(const float4*)(B + (size_t)(k0 + br0 + 8) * DIM + bn + bc0);
    };
    auto store_s = [&]() {
        As[ac0 + 0][ar0] = aR0.x; As[ac0 + 1][ar0] = aR0.y;
        As[ac0 + 2][ar0] = aR0.z; As[ac0 + 3][ar0] = aR0.w;
        As[ac0 + 0][ar0 + 64] = aR1.x; As[ac0 + 1][ar0 + 64] = aR1.y;
        As[ac0 + 2][ar0 + 64] = aR1.z; As[ac0 + 3][ar0 + 64] = aR1.w;
        *(float4*)&Bs[br0][bc0]     = bR0;
        *(float4*)&Bs[br0 + 8][bc0] = bR1;
    };
    auto compute = [&]() {
#pragma unroll
        for (int kk = 0; kk < 16; kk++) {
            float4 a0 = *(const float4*)&As[kk][tm * 8];
            float4 a1 = *(const float4*)&As[kk][tm * 8 + 4];
            ulonglong2 b0 = *(const ulonglong2*)&Bs[kk][tn * 8];
            ulonglong2 b1 = *(const ulonglong2*)&Bs[kk][tn * 8 + 4];
            unsigned long long bp0 = b0.x, bp1 = b0.y, bp2 = b1.x, bp3 = b1.y;
            float av[8] = {a0.x, a0.y, a0.z, a0.w, a1.x, a1.y, a1.z, a1.w};
#pragma unroll
            for (int mm = 0; mm < 8; mm++) {
                unsigned long long ad = pk2(av[mm]);
                fma2(acc[mm][0], ad, bp0);
                fma2(acc[mm][1], ad, bp1);
                fma2(acc[mm][2], ad, bp2);
                fma2(acc[mm][3], ad, bp3);
            }
        }
    };

    load_g(0);
    store_s();
    __syncthreads();
    for (int k0 = 16; k0 < DIM; k0 += 16) {
        load_g(k0);
        compute();
        __syncthreads();
        store_s();
        __syncthreads();
    }
    compute();

#pragma unroll
    for (int mm = 0; mm < 8; mm++) {
        float2* cp = (float2*)(C + (size_t)(bm + tm * 8 + mm) * DIM + bn + tn * 8);
#pragma unroll
        for (int np = 0; np < 4; np++) cp[np] = *(float2*)&acc[mm][np];
    }
}

// ---------------- per-(relation,node) Q/K projections: warp per row ----------------
template <int H>
__global__ void k_qk(const float* __restrict__ q, const float* __restrict__ k) {
    int gw   = (blockIdx.x * blockDim.x + threadIdx.x) >> 5;
    int lane = threadIdx.x & 31;
    if (gw >= N_REL * N_NODES) return;
    const float* row = g_xr + (size_t)gw * DIM;
    float qa[H], ka[H];
#pragma unroll
    for (int h = 0; h < H; h++) { qa[h] = 0.f; ka[h] = 0.f; }
    for (int c = lane; c < DIM; c += 32) {
        float v = row[c];
#pragma unroll
        for (int h = 0; h < H; h++) {
            qa[h] = fmaf(v, __ldg(&q[c * H + h]), qa[h]);
            ka[h] = fmaf(v, __ldg(&k[c * H + h]), ka[h]);
        }
    }
#pragma unroll
    for (int h = 0; h < H; h++) {
#pragma unroll
        for (int s = 16; s; s >>= 1) {
            qa[h] += __shfl_xor_sync(0xffffffffu, qa[h], s);
            ka[h] += __shfl_xor_sync(0xffffffffu, ka[h], s);
        }
    }
    if (lane == 0) {
#pragma unroll
        for (int h = 0; h < H; h++) {
            g_Q[gw * H + h] = qa[h];
            g_K[gw * H + h] = ka[h];
        }
    }
}

// ---------------- per-edge attention logits (leaky relu) ----------------
template <int H>
__global__ void k_alpha() {
    int e = blockIdx.x * blockDim.x + threadIdx.x;
    if (e >= N_EDGES) return;
    int et = g_et[e], s = g_src[e], d = g_dst[e];
    int bq = (et * N_NODES + d) * H;
    int bk = (et * N_NODES + s) * H;
#pragma unroll
    for (int h = 0; h < H; h++) {
        float v = g_Q[bq + h] + g_K[bk + h];
        g_alpha[e * H + h] = (v >= 0.f) ? v : 0.2f * v;
    }
}

// ---------------- per-node segment softmax + weighted aggregation ----------------
template <int H, int OUT, bool ELU, bool TO_OUT>
__global__ __launch_bounds__(128) void k_agg(const float* __restrict__ bias,
                                             float* __restrict__ outp) {
    int n   = blockIdx.x;
    int off = g_off[n];
    int cnt = g_off[n + 1] - off;

    __shared__ float sm_m[H], sm_rz[H];
    __shared__ int   sm_row[128];
    __shared__ float sm_a[128 * H];

    int tid = threadIdx.x, lane = tid & 31, w = tid >> 5;

    if (w < H) {  // one warp per head: max + sum-exp over this node's edges
        float mx = -3.0e38f;
        for (int i = lane; i < cnt; i += 32) {
            int e = g_eperm[off + i];
            mx = fmaxf(mx, g_alpha[e * H + w]);
        }
#pragma unroll
        for (int s = 16; s; s >>= 1) mx = fmaxf(mx, __shfl_xor_sync(0xffffffffu, mx, s));
        float z = 0.f;
        for (int i = lane; i < cnt; i += 32) {
            int e = g_eperm[off + i];
            z += expf(g_alpha[e * H + w] - mx);
        }
#pragma unroll
        for (int s = 16; s; s >>= 1) z += __shfl_xor_sync(0xffffffffu, z, s);
        if (lane == 0) { sm_m[w] = mx; sm_rz[w] = 1.f / (z + 1e-16f); }
    }
    __syncthreads();

    float acc[6] = {0.f, 0.f, 0.f, 0.f, 0.f, 0.f};
    int hidx[6];
#pragma unroll
    for (int j = 0; j < 6; j++) hidx[j] = (tid + j * 128) / OUT;

    for (int base = 0; base < cnt; base += 128) {
        int c = cnt - base;
        if (c > 128) c = 128;
        if (tid < c) {
            int e = g_eperm[off + base + tid];
            sm_row[tid] = (g_et[e] * N_NODES + g_src[e]) * DIM;
#pragma unroll
            for (int h = 0; h < H; h++)
                sm_a[tid * H + h] = expf(g_alpha[e * H + h] - sm_m[h]) * sm_rz[h];
        }
        __syncthreads();
        for (int i = 0; i < c; i++) {
            const float* row = g_xr + sm_row[i];
#pragma unroll
            for (int j = 0; j < 6; j++)
                acc[j] = fmaf(sm_a[i * H + hidx[j]], row[tid + j * 128], acc[j]);
        }
        __syncthreads();
    }

    float* dst = TO_OUT ? outp : g_h;
    size_t ob = (size_t)n * DIM;
#pragma unroll
    for (int j = 0; j < 6; j++) {
        int cch = tid + j * 128;
        float v = acc[j] + bias[cch];
        if (ELU) v = (v > 0.f) ? v : expm1f(v);
        dst[ob + cch] = v;
    }
}

// ---------------- launch ----------------
extern "C" void kernel_launch(void* const* d_in, const int* in_sizes, int n_in,
                              void* d_out, int out_size) {
    const float* x  = (const float*)d_in[0];
    const int*   ei = (const int*)d_in[1];
    const int*   et = (const int*)d_in[2];
    const float* W1 = (const float*)d_in[3];
    const float* q1 = (const float*)d_in[4];
    const float* k1 = (const float*)d_in[5];
    const float* b1 = (const float*)d_in[6];
    const float* W2 = (const float*)d_in[7];
    const float* q2 = (const float*)d_in[8];
    const float* k2 = (const float*)d_in[9];
    const float* b2 = (const float*)d_in[10];
    float* out = (float*)d_out;

    // CSR build (shared by both layers)
    k_zero_deg<<<(N_NODES + 255) / 256, 256>>>();
    k_prep_edges<<<(N_EDGES + 255) / 256, 256>>>(ei, et);
    k_scan<<<1, 1024>>>();
    k_scatter<<<(N_EDGES + 255) / 256, 256>>>();

    dim3 ggrid(DIM / 128, N_NODES / 128, N_REL);

    // ---- layer 1: H=4, OUT=192, ELU, writes g_h ----
    k_gemm<false><<<ggrid, 256>>>(x, W1);
    k_qk<H1><<<(N_REL * N_NODES) / 8, 256>>>(q1, k1);
    k_alpha<H1><<<(N_EDGES + 255) / 256, 256>>>();
    k_agg<H1, O1, true, false><<<N_NODES, 128>>>(b1, nullptr);

    // ---- layer 2: H=1, OUT=768, no ELU, writes d_out ----
    k_gemm<true><<<ggrid, 256>>>(nullptr, W2);
    k_qk<H2><<<(N_REL * N_NODES) / 8, 256>>>(q2, k2);
    k_alpha<H2><<<(N_EDGES + 255) / 256, 256>>>();
    k_agg<H2, O2, false, true><<<N_NODES, 128>>>(b2, out);
}

// round 4
// speedup vs baseline: 2.1943x; 2.1943x over previous
#include <cuda_runtime.h>
#include <cuda_bf16.h>

#define N_NODES 32768
#define N_EDGES 160000
#define DIM     768
#define N_REL   3
#define H1      4
#define O1      192
#define H2      1
#define O2      768

// ---- mma GEMM tiling ----
#define MT 128
#define NT 128
#define KC 64
#define NCHUNK (DIM / KC)     // 12
#define ST_A_HI 0
#define ST_A_LO 16384
#define ST_B_HI 32768
#define ST_B_LO 49152
#define STAGE_SZ 65536
#define SMEM_TOTAL (2 * STAGE_SZ)   // 131072

// ---------------- scratch ----------------
__device__ float g_xr[(size_t)N_REL * N_NODES * DIM];
__device__ float g_h [(size_t)N_NODES * DIM];
__device__ float g_Q [N_REL * N_NODES * H1];
__device__ float g_K [N_REL * N_NODES * H1];
__device__ float g_alpha[N_EDGES * H1];
__device__ int   g_src[N_EDGES], g_dst[N_EDGES], g_et[N_EDGES];
__device__ int   g_deg[N_NODES];
__device__ int   g_off[N_NODES + 1];
__device__ int   g_pos[N_NODES];
__device__ int   g_eperm[N_EDGES];
__device__ __align__(16) __nv_bfloat16 g_Ahi[(size_t)N_NODES * DIM];
__device__ __align__(16) __nv_bfloat16 g_Alo[(size_t)N_NODES * DIM];
__device__ __align__(16) __nv_bfloat16 g_Bthi[(size_t)N_REL * DIM * DIM];  // [r][n][d]
__device__ __align__(16) __nv_bfloat16 g_Btlo[(size_t)N_REL * DIM * DIM];

// ---------------- PTX helpers ----------------
__device__ __forceinline__ unsigned smem_u32(const void* p) {
    unsigned a;
    asm("{ .reg .u64 t; cvta.to.shared.u64 t, %1; cvt.u32.u64 %0, t; }" : "=r"(a) : "l"(p));
    return a;
}
__device__ __forceinline__ void cp16(unsigned d, const void* s) {
    asm volatile("cp.async.cg.shared.global [%0], [%1], 16;" :: "r"(d), "l"(s));
}
__device__ __forceinline__ unsigned sw128(unsigned o) { return o ^ ((o >> 3) & 0x70); }

__device__ __forceinline__ void ldsm4(unsigned* r, unsigned addr) {
    asm volatile("ldmatrix.sync.aligned.m8n8.x4.shared.b16 {%0,%1,%2,%3}, [%4];"
                 : "=r"(r[0]), "=r"(r[1]), "=r"(r[2]), "=r"(r[3]) : "r"(addr));
}
__device__ __forceinline__ void mma16816(float* c, const unsigned* a, const unsigned* b) {
    asm volatile(
        "mma.sync.aligned.m16n8k16.row.col.f32.bf16.bf16.f32 "
        "{%0,%1,%2,%3}, {%4,%5,%6,%7}, {%8,%9}, {%0,%1,%2,%3};"
        : "+f"(c[0]), "+f"(c[1]), "+f"(c[2]), "+f"(c[3])
        : "r"(a[0]), "r"(a[1]), "r"(a[2]), "r"(a[3]), "r"(b[0]), "r"(b[1]));
}

// ---------------- edge preprocessing (known-correct) ----------------
__global__ void k_zero_deg() {
    int i = blockIdx.x * blockDim.x + threadIdx.x;
    if (i < N_NODES) g_deg[i] = 0;
}
__global__ void k_prep_edges(const int* __restrict__ ei, const int* __restrict__ et) {
    int e = blockIdx.x * blockDim.x + threadIdx.x;
    if (e >= N_EDGES) return;
    int s = ei[e] & (N_NODES - 1);
    int d = ei[N_EDGES + e] & (N_NODES - 1);
    int t = et[e];
    t = (t < 0) ? 0 : (t >= N_REL ? N_REL - 1 : t);
    g_src[e] = s; g_dst[e] = d; g_et[e] = t;
    atomicAdd(&g_deg[d], 1);
}
__global__ void k_scan() {
    __shared__ int ps[1024];
    int tid = threadIdx.x, base = tid * 32, local[32], s = 0;
#pragma unroll
    for (int j = 0; j < 32; j++) { local[j] = g_deg[base + j]; s += local[j]; }
    ps[tid] = s;
    __syncthreads();
    for (int st = 1; st < 1024; st <<= 1) {
        int v = (tid >= st) ? ps[tid - st] : 0;
        __syncthreads(); ps[tid] += v; __syncthreads();
    }
    int run = ps[tid] - s;
#pragma unroll
    for (int j = 0; j < 32; j++) { g_off[base + j] = run; g_pos[base + j] = run; run += local[j]; }
    if (tid == 1023) g_off[N_NODES] = run;
}
__global__ void k_scatter() {
    int e = blockIdx.x * blockDim.x + threadIdx.x;
    if (e >= N_EDGES) return;
    int p = atomicAdd(&g_pos[g_dst[e]], 1);
    g_eperm[p] = e;
}

// ---------------- bf16 hi/lo split of A (x or g_h) ----------------
template <bool FROM_H>
__global__ void k_splitA(const float4* __restrict__ in_x) {
    const float4* in = FROM_H ? (const float4*)g_h : in_x;
    int i = blockIdx.x * blockDim.x + threadIdx.x;
    float4 v = in[i];
    __nv_bfloat16 h0 = __float2bfloat16(v.x), h1 = __float2bfloat16(v.y),
                  h2 = __float2bfloat16(v.z), h3 = __float2bfloat16(v.w);
    __nv_bfloat16 l0 = __float2bfloat16(v.x - __bfloat162float(h0));
    __nv_bfloat16 l1 = __float2bfloat16(v.y - __bfloat162float(h1));
    __nv_bfloat16 l2 = __float2bfloat16(v.z - __bfloat162float(h2));
    __nv_bfloat16 l3 = __float2bfloat16(v.w - __bfloat162float(h3));
    ((__nv_bfloat162*)g_Ahi)[2 * i]     = __nv_bfloat162(h0, h1);
    ((__nv_bfloat162*)g_Ahi)[2 * i + 1] = __nv_bfloat162(h2, h3);
    ((__nv_bfloat162*)g_Alo)[2 * i]     = __nv_bfloat162(l0, l1);
    ((__nv_bfloat162*)g_Alo)[2 * i + 1] = __nv_bfloat162(l2, l3);
}

// ---------------- transpose + split W -> Bt [r][n][d] ----------------
__global__ void k_splitW(const float* __restrict__ W) {
    __shared__ float tile[32][33];
    int r = blockIdx.z, d0 = blockIdx.y * 32, f0 = blockIdx.x * 32;
    int tx = threadIdx.x, ty = threadIdx.y;
    const float* Wr = W + (size_t)r * DIM * DIM;
#pragma unroll
    for (int j = 0; j < 32; j += 8)
        tile[ty + j][tx] = Wr[(size_t)(d0 + ty + j) * DIM + f0 + tx];
    __syncthreads();
#pragma unroll
    for (int j = 0; j < 32; j += 8) {
        int n = f0 + ty + j, d = d0 + tx;
        float v = tile[tx][ty + j];
        __nv_bfloat16 h = __float2bfloat16(v);
        __nv_bfloat16 l = __float2bfloat16(v - __bfloat162float(h));
        size_t o = ((size_t)r * DIM + n) * DIM + d;
        g_Bthi[o] = h;
        g_Btlo[o] = l;
    }
}

// ---------------- HMMA GEMM: g_xr[r] = A @ Bt[r]^T  (both K-contig, SW128) ----------------
__device__ __forceinline__ void load_chunk(unsigned sb, int k0,
        const __nv_bfloat16* aH, const __nv_bfloat16* aL,
        const __nv_bfloat16* bH, const __nv_bfloat16* bL, int t) {
#pragma unroll
    for (int j = 0; j < 2; j++) {               // A: 1024 16B units (128 rows x 8)
        int u = j * 512 + t;
        int row = u >> 3, kc = u & 7;
        unsigned so = sw128(row * 128 + kc * 16);
        size_t go = (size_t)row * DIM + k0 + kc * 8;
        cp16(sb + ST_A_HI + so, aH + go);
        cp16(sb + ST_A_LO + so, aL + go);
    }
#pragma unroll
    for (int j = 0; j < 2; j++) {               // B: 1024 units (128 n-rows x 8)
        int u = j * 512 + t;
        int row = u >> 3, kc = u & 7;
        unsigned so = sw128(row * 128 + kc * 16);
        size_t go = (size_t)row * DIM + k0 + kc * 8;
        cp16(sb + ST_B_HI + so, bH + go);
        cp16(sb + ST_B_LO + so, bL + go);
    }
}

__global__ __launch_bounds__(512, 1) void k_gemm_mma() {
    extern __shared__ char smem[];
    unsigned sb = smem_u32(smem);
    int t = threadIdx.x, wid = t >> 5, lane = t & 31;
    int wm = wid & 3, wn = wid >> 2;            // warp grid 4(m) x 4(n), 32x32 warp tile
    int nt6 = blockIdx.x % 6, r = blockIdx.x / 6;
    int bm = blockIdx.y * MT, bn = nt6 * NT;

    const __nv_bfloat16* aH = g_Ahi + (size_t)bm * DIM;
    const __nv_bfloat16* aL = g_Alo + (size_t)bm * DIM;
    const __nv_bfloat16* bH = g_Bthi + ((size_t)r * DIM + bn) * DIM;
    const __nv_bfloat16* bL = g_Btlo + ((size_t)r * DIM + bn) * DIM;

    float acc[2][4][4];
#pragma unroll
    for (int i = 0; i < 2; i++)
#pragma unroll
        for (int j = 0; j < 4; j++)
#pragma unroll
            for (int k = 0; k < 4; k++) acc[i][j][k] = 0.f;

    // per-thread ldmatrix address components
    unsigned aRow = (unsigned)(wm * 32 + (lane & 15)) * 128;   // + mt*16*128
    unsigned aKc  = (unsigned)(lane >> 4);                     // + ks*2
    unsigned bRow = (unsigned)(wn * 32 + (lane & 7) + ((lane >> 4) << 3)) * 128;  // + bt*16*128
    unsigned bKc  = (unsigned)((lane >> 3) & 1);               // + ks*2

    load_chunk(sb, 0, aH, aL, bH, bL, t);
    asm volatile("cp.async.commit_group;" ::: "memory");

    for (int i = 0; i < NCHUNK; i++) {
        unsigned stg = sb + (unsigned)(i & 1) * STAGE_SZ;
        if (i + 1 < NCHUNK) {
            load_chunk(sb + (unsigned)((i + 1) & 1) * STAGE_SZ, (i + 1) * KC,
                       aH, aL, bH, bL, t);
            asm volatile("cp.async.commit_group;" ::: "memory");
            asm volatile("cp.async.wait_group 1;" ::: "memory");
        } else {
            asm volatile("cp.async.wait_group 0;" ::: "memory");
        }
        __syncthreads();

#pragma unroll
        for (int ks = 0; ks < 4; ks++) {
            unsigned aHi[2][4], aLo[2][4], bHi[2][4], bLo[2][4];
#pragma unroll
            for (int mt = 0; mt < 2; mt++) {
                unsigned off = sw128(aRow + mt * 2048 + (aKc + ks * 2) * 16);
                ldsm4(aHi[mt], stg + ST_A_HI + off);
                ldsm4(aLo[mt], stg + ST_A_LO + off);
            }
#pragma unroll
            for (int bt = 0; bt < 2; bt++) {
                unsigned off = sw128(bRow + bt * 2048 + (bKc + ks * 2) * 16);
                ldsm4(bHi[bt], stg + ST_B_HI + off);
                ldsm4(bLo[bt], stg + ST_B_LO + off);
            }
#pragma unroll
            for (int mt = 0; mt < 2; mt++)
#pragma unroll
                for (int nt = 0; nt < 4; nt++) {
                    int bt = nt >> 1, rg = (nt & 1) * 2;
                    mma16816(acc[mt][nt], aHi[mt], &bHi[bt][rg]);
                    mma16816(acc[mt][nt], aHi[mt], &bLo[bt][rg]);
                    mma16816(acc[mt][nt], aLo[mt], &bHi[bt][rg]);
                }
        }
        __syncthreads();
    }

    // epilogue
    float* C = g_xr + ((size_t)r * N_NODES + bm) * DIM + bn;
#pragma unroll
    for (int mt = 0; mt < 2; mt++)
#pragma unroll
        for (int nt = 0; nt < 4; nt++) {
            int row = wm * 32 + mt * 16 + (lane >> 2);
            int col = wn * 32 + nt * 8 + (lane & 3) * 2;
            *(float2*)(C + (size_t)row * DIM + col) =
                make_float2(acc[mt][nt][0], acc[mt][nt][1]);
            *(float2*)(C + (size_t)(row + 8) * DIM + col) =
                make_float2(acc[mt][nt][2], acc[mt][nt][3]);
        }
}

// ---------------- per-(relation,node) Q/K projections ----------------
template <int H>
__global__ void k_qk(const float* __restrict__ q, const float* __restrict__ k) {
    int gw = (blockIdx.x * blockDim.x + threadIdx.x) >> 5;
    int lane = threadIdx.x & 31;
    if (gw >= N_REL * N_NODES) return;
    const float* row = g_xr + (size_t)gw * DIM;
    float qa[H], ka[H];
#pragma unroll
    for (int h = 0; h < H; h++) { qa[h] = 0.f; ka[h] = 0.f; }
    for (int c = lane; c < DIM; c += 32) {
        float v = row[c];
#pragma unroll
        for (int h = 0; h < H; h++) {
            qa[h] = fmaf(v, __ldg(&q[c * H + h]), qa[h]);
            ka[h] = fmaf(v, __ldg(&k[c * H + h]), ka[h]);
        }
    }
#pragma unroll
    for (int h = 0; h < H; h++) {
#pragma unroll
        for (int s = 16; s; s >>= 1) {
            qa[h] += __shfl_xor_sync(0xffffffffu, qa[h], s);
            ka[h] += __shfl_xor_sync(0xffffffffu, ka[h], s);
        }
    }
    if (lane == 0) {
#pragma unroll
        for (int h = 0; h < H; h++) { g_Q[gw * H + h] = qa[h]; g_K[gw * H + h] = ka[h]; }
    }
}

template <int H>
__global__ void k_alpha() {
    int e = blockIdx.x * blockDim.x + threadIdx.x;
    if (e >= N_EDGES) return;
    int et = g_et[e], s = g_src[e], d = g_dst[e];
    int bq = (et * N_NODES + d) * H;
    int bk = (et * N_NODES + s) * H;
#pragma unroll
    for (int h = 0; h < H; h++) {
        float v = g_Q[bq + h] + g_K[bk + h];
        g_alpha[e * H + h] = (v >= 0.f) ? v : 0.2f * v;
    }
}

template <int H, int OUT, bool ELU, bool TO_OUT>
__global__ __launch_bounds__(128) void k_agg(const float* __restrict__ bias,
                                             float* __restrict__ outp) {
    int n = blockIdx.x;
    int off = g_off[n];
    int cnt = g_off[n + 1] - off;

    __shared__ float sm_m[H], sm_rz[H];
    __shared__ int   sm_row[128];
    __shared__ float sm_a[128 * H];

    int tid = threadIdx.x, lane = tid & 31, w = tid >> 5;

    if (w < H) {
        float mx = -3.0e38f;
        for (int i = lane; i < cnt; i += 32) {
            int e = g_eperm[off + i];
            mx = fmaxf(mx, g_alpha[e * H + w]);
        }
#pragma unroll
        for (int s = 16; s; s >>= 1) mx = fmaxf(mx, __shfl_xor_sync(0xffffffffu, mx, s));
        float z = 0.f;
        for (int i = lane; i < cnt; i += 32) {
            int e = g_eperm[off + i];
            z += expf(g_alpha[e * H + w] - mx);
        }
#pragma unroll
        for (int s = 16; s; s >>= 1) z += __shfl_xor_sync(0xffffffffu, z, s);
        if (lane == 0) { sm_m[w] = mx; sm_rz[w] = 1.f / (z + 1e-16f); }
    }
    __syncthreads();

    float acc[6] = {0.f, 0.f, 0.f, 0.f, 0.f, 0.f};
    int hidx[6];
#pragma unroll
    for (int j = 0; j < 6; j++) hidx[j] = (tid + j * 128) / OUT;

    for (int base = 0; base < cnt; base += 128) {
        int c = cnt - base;
        if (c > 128) c = 128;
        if (tid < c) {
            int e = g_eperm[off + base + tid];
            sm_row[tid] = (g_et[e] * N_NODES + g_src[e]) * DIM;
#pragma unroll
            for (int h = 0; h < H; h++)
                sm_a[tid * H + h] = expf(g_alpha[e * H + h] - sm_m[h]) * sm_rz[h];
        }
        __syncthreads();
        for (int i = 0; i < c; i++) {
            const float* row = g_xr + sm_row[i];
#pragma unroll
            for (int j = 0; j < 6; j++)
                acc[j] = fmaf(sm_a[i * H + hidx[j]], row[tid + j * 128], acc[j]);
        }
        __syncthreads();
    }

    float* dst = TO_OUT ? outp : g_h;
    size_t ob = (size_t)n * DIM;
#pragma unroll
    for (int j = 0; j < 6; j++) {
        int cch = tid + j * 128;
        float v = acc[j] + bias[cch];
        if (ELU) v = (v > 0.f) ? v : expm1f(v);
        dst[ob + cch] = v;
    }
}

// ---------------- launch ----------------
extern "C" void kernel_launch(void* const* d_in, const int* in_sizes, int n_in,
                              void* d_out, int out_size) {
    const float* x  = (const float*)d_in[0];
    const int*   ei = (const int*)d_in[1];
    const int*   et = (const int*)d_in[2];
    const float* W1 = (const float*)d_in[3];
    const float* q1 = (const float*)d_in[4];
    const float* k1 = (const float*)d_in[5];
    const float* b1 = (const float*)d_in[6];
    const float* W2 = (const float*)d_in[7];
    const float* q2 = (const float*)d_in[8];
    const float* k2 = (const float*)d_in[9];
    const float* b2 = (const float*)d_in[10];
    float* out = (float*)d_out;

    cudaFuncSetAttribute(k_gemm_mma, cudaFuncAttributeMaxDynamicSharedMemorySize, SMEM_TOTAL);

    // CSR build
    k_zero_deg<<<(N_NODES + 255) / 256, 256>>>();
    k_prep_edges<<<(N_EDGES + 255) / 256, 256>>>(ei, et);
    k_scan<<<1, 1024>>>();
    k_scatter<<<(N_EDGES + 255) / 256, 256>>>();

    dim3 ggrid(6 * N_REL, N_NODES / MT);       // x: r*6 + n-tile, y: m-tile
    dim3 wgrid(DIM / 32, DIM / 32, N_REL);
    dim3 wblk(32, 8);
    int  ablocks = (N_NODES * DIM / 4) / 256;

    // ---- layer 1 ----
    k_splitW<<<wgrid, wblk>>>(W1);
    k_splitA<false><<<ablocks, 256>>>((const float4*)x);
    k_gemm_mma<<<ggrid, 512, SMEM_TOTAL>>>();
    k_qk<H1><<<(N_REL * N_NODES) / 8, 256>>>(q1, k1);
    k_alpha<H1><<<(N_EDGES + 255) / 256, 256>>>();
    k_agg<H1, O1, true, false><<<N_NODES, 128>>>(b1, nullptr);

    // ---- layer 2 ----
    k_splitW<<<wgrid, wblk>>>(W2);
    k_splitA<true><<<ablocks, 256>>>(nullptr);
    k_gemm_mma<<<ggrid, 512, SMEM_TOTAL>>>();
    k_qk<H2><<<(N_REL * N_NODES) / 8, 256>>>(q2, k2);
    k_alpha<H2><<<(N_EDGES + 255) / 256, 256>>>();
    k_agg<H2, O2, false, true><<<N_NODES, 128>>>(b2, out);
}